// round 17
// baseline (speedup 1.0000x reference)
#include <cuda_runtime.h>

namespace {

constexpr int NQ     = 12;
constexpr int DEPTH  = 6;
constexpr int NSTATE = 1 << NQ;        // 4096
constexpr int NT     = 256;            // threads per CTA
constexpr int PT     = NSTATE / NT;    // 16 amplitudes per thread
constexpr int NPAD   = NSTATE + (NSTATE >> 4);   // 4352: pad-17 rows

typedef unsigned long long u64;

// Padded linear layout: phys(idx) = idx + (idx>>4) = 17*(idx>>4) + (idx&15).

__device__ __forceinline__ float2 cmul(float2 a, float2 b) {
    float2 r;
    r.x = fmaf(a.x, b.x, -(a.y * b.y));
    r.y = fmaf(a.x, b.y, a.y * b.x);
    return r;
}
__device__ __forceinline__ float2 cmulc(float2 a, float2 b) {  // a * conj(b)
    float2 r;
    r.x = fmaf(a.x, b.x,  a.y * b.y);
    r.y = fmaf(a.y, b.x, -(a.x * b.y));
    return r;
}

// ---- packed f32x2 helpers ----
__device__ __forceinline__ u64 pack2s(float v) {               // {v, v}
    u64 u; asm("mov.b64 %0, {%1,%1};" : "=l"(u) : "f"(v)); return u;
}
__device__ __forceinline__ u64 f2u(float2 v) {                 // {x, y}
    u64 u; asm("mov.b64 %0, {%1,%2};" : "=l"(u) : "f"(v.x), "f"(v.y)); return u;
}
__device__ __forceinline__ float2 u2f(u64 u) {
    float2 v; asm("mov.b64 {%0,%1}, %2;" : "=f"(v.x), "=f"(v.y) : "l"(u)); return v;
}
__device__ __forceinline__ u64 mul2(u64 a, u64 b) {
    u64 r; asm("mul.rn.f32x2 %0, %1, %2;" : "=l"(r) : "l"(a), "l"(b)); return r;
}
__device__ __forceinline__ u64 fma2(u64 a, u64 b, u64 c) {
    u64 r; asm("fma.rn.f32x2 %0, %1, %2, %3;" : "=l"(r) : "l"(a), "l"(b), "l"(c)); return r;
}
// packed shear pair: na = a - tv*b ; nb = tv*a + b   (2 FFMA2)
__device__ __forceinline__ void sh2(u64& a, u64& b, u64 tv2, u64 ntv2) {
    u64 na = fma2(ntv2, b, a);
    u64 nb = fma2(tv2,  a, b);
    a = na; b = nb;
}
// 4 wires over local bits 3..0, packed
__device__ __forceinline__ void gate4p(u64* s, float t0, float t1, float t2, float t3) {
    const u64 p0 = pack2s(t0), n0 = pack2s(-t0);
    #pragma unroll
    for (int m = 0; m < 8; ++m) sh2(s[m], s[m + 8], p0, n0);
    const u64 p1 = pack2s(t1), n1 = pack2s(-t1);
    #pragma unroll
    for (int m = 0; m < 8; ++m) {
        int i0 = ((m >> 2) << 3) | (m & 3);
        sh2(s[i0], s[i0 | 4], p1, n1);
    }
    const u64 p2 = pack2s(t2), n2 = pack2s(-t2);
    #pragma unroll
    for (int m = 0; m < 8; ++m) {
        int i0 = ((m >> 1) << 2) | (m & 1);
        sh2(s[i0], s[i0 | 2], p2, n2);
    }
    const u64 p3 = pack2s(t3), n3 = pack2s(-t3);
    #pragma unroll
    for (int m = 0; m < 8; ++m) {
        int i0 = m << 1;
        sh2(s[i0], s[i0 | 1], p3, n3);
    }
}

__global__ void __launch_bounds__(NT, 4) qsim_kernel(const float* __restrict__ x,
                                                     const float* __restrict__ params,
                                                     float* __restrict__ out)
{
    __shared__ float2 sS[NPAD];            // state, padded layout (34.0 KB)
    __shared__ float2 sU0[NQ][4];          // layer-0 full matrices (batch-dependent)
    __shared__ float  sT [DEPTH][NQ];      // shear coeff t = s'/c' (<=1), d>=1
    __shared__ float  sSc[DEPTH][NQ];      // per-gate scale c'
    __shared__ float2 sB1[DEPTH][NQ];      // B-diag b1 (b0 == 1 gauge), d>=1
    __shared__ float2 sA0[DEPTH][NQ];      // A-diag a0 (temp, for G0)
    __shared__ float2 sG [DEPTH][NQ];      // g = a1*conj(a0)
    __shared__ float2 sG0[DEPTH];          // prod_i a0[d][i], d=1..4
    __shared__ float  sCd[DEPTH];          // prod_i scale[d][i], d=1..5
    __shared__ int    sM [DEPTH];          // per-layer X-flip mask (wire i -> bit 11-i)
    __shared__ float2 sPhiA[DEPTH - 1][16];     // phase over t bits [7:4]
    __shared__ float2 sPhiB[DEPTH - 1][2][16];  // phase over t bits [3:0] (x bit4)
    __shared__ float2 sThiP[DEPTH - 1][2][16];  // r-phase {x,y}
    __shared__ float2 sThiQ[DEPTH - 1][2][16];  // r-phase dual {-y,x}
    __shared__ float2 sW1P[2][16];              // layer-1 fused table {x,y}
    __shared__ float2 sW1Q[2][16];              // layer-1 fused table dual {-y,x}
    __shared__ float  sRed[NT / 32][NQ];

    const int t = threadIdx.x;
    const int b = blockIdx.x;

    if (t < DEPTH) sM[t] = 0;
    __syncthreads();

    // ================= Stage A: build gates; decompose U = (A*RY*B)*X =======
    if (t < DEPTH * NQ) {
        const int d = t / NQ, i = t % NQ;
        const float* pp = params + (d * NQ + i) * 3;
        float sa, ca, sb, cb, sg, cg;
        sincosf(0.5f * pp[0], &sa, &ca);
        sincosf(0.5f * pp[1], &sb, &cb);
        sincosf(0.5f * pp[2], &sg, &cg);
        float2 m00 = {  cb * ca, -sb * ca };
        float2 m01 = { -cb * sa,  sb * sa };
        float2 m10 = {  cb * sa,  sb * sa };
        float2 m11 = {  cb * ca,  sb * ca };
        float2 u00 = { cg * m00.x + sg * m10.y, cg * m00.y - sg * m10.x };
        float2 u01 = { cg * m01.x + sg * m11.y, cg * m01.y - sg * m11.x };
        float2 u10 = { sg * m00.y + cg * m10.x, -sg * m00.x + cg * m10.y };
        float2 u11 = { sg * m01.y + cg * m11.x, -sg * m01.x + cg * m11.y };
        if (d == 0) {
            float sx, cx;
            sincosf(0.5f * x[b * NQ + i], &sx, &cx);
            float2 v00 = { cx * u00.x + sx * u01.y,  cx * u00.y - sx * u01.x };
            float2 v01 = { sx * u00.y + cx * u01.x, -sx * u00.x + cx * u01.y };
            float2 v10 = { cx * u10.x + sx * u11.y,  cx * u10.y - sx * u11.x };
            float2 v11 = { sx * u10.y + cx * u11.x, -sx * u10.x + cx * u11.y };
            sU0[i][0] = v00; sU0[i][1] = v01; sU0[i][2] = v10; sU0[i][3] = v11;
        } else {
            float n00 = fmaf(u00.x, u00.x, u00.y * u00.y);
            float n10 = fmaf(u10.x, u10.x, u10.y * u10.y);
            bool swp = n10 > n00;     // V = U*X (column swap) so c' >= s'
            float2 v00, v10, v11;
            if (swp) { v00 = u01; v10 = u11; v11 = u10; atomicOr(&sM[d], 1 << (11 - i)); }
            else     { v00 = u00; v10 = u10; v11 = u11; }
            float c = sqrtf(fmaf(v00.x, v00.x, v00.y * v00.y));
            float s = sqrtf(fmaf(v10.x, v10.x, v10.y * v10.y));
            float ic = 1.0f / c;
            float2 a0 = { v00.x * ic, v00.y * ic };
            float2 a1, b1;
            if (s < 1e-12f) {
                a1 = { v11.x * ic, v11.y * ic };
                b1 = { 1.f, 0.f };
            } else {
                float is = 1.0f / s;
                a1 = { v10.x * is, v10.y * is };
                float2 tb = cmulc(v11, a1);
                b1 = { tb.x * ic, tb.y * ic };
            }
            sT [d][i] = s * ic;
            sSc[d][i] = c;
            sB1[d][i] = b1;
            sA0[d][i] = a0;
            sG [d][i] = cmulc(a1, a0);
        }
    }
    __syncthreads();

    // ================= Stage B: per-layer products =========================
    if (t >= 1 && t <= 5) {
        float cs = 1.f;
        #pragma unroll
        for (int i = 0; i < NQ; ++i) cs *= sSc[t][i];
        sCd[t] = cs;
        if (t <= 4) {
            float2 p = { 1.f, 0.f };
            #pragma unroll
            for (int i = 0; i < NQ; ++i) p = cmul(p, sA0[t][i]);
            sG0[t] = p;
        }
    }
    __syncthreads();

    // ================= Stage C: factorized diagonal tables =================
    // dst = (r<<8)|t ; src = gray(dst) ^ gm_d.
    // D_d(dst) = PhiA[t>>4] * PhiB[bit4(t)][t&15] * Thi[bit7(t)][r].
    if (t < (DEPTH - 1) * 16) {            // PhiA: t bits 7..4 (wires 4..7)
        const int k = t >> 4, h = t & 15;
        const int d = k + 1;
        const int mm = sM[d];
        const int gm = mm ^ (mm >> 1);
        float2 P = (d >= 2) ? sG0[d - 1] : make_float2(1.f, 0.f);
        const float cd = sCd[d];
        P.x *= cd; P.y *= cd;
        #pragma unroll
        for (int i = 4; i <= 7; ++i)       // wire i -> t bit (11-i) = h bit (7-i)
            if ((h >> (7 - i)) & 1) P = cmul(P, sB1[d][i]);
        if (d >= 2) {                      // couplings i=5,6,7
            if (((h >> 2) ^ (h >> 3) ^ (gm >> 6)) & 1) P = cmul(P, sG[d - 1][5]);
            if (((h >> 1) ^ (h >> 2) ^ (gm >> 5)) & 1) P = cmul(P, sG[d - 1][6]);
            if (((h >> 0) ^ (h >> 1) ^ (gm >> 4)) & 1) P = cmul(P, sG[d - 1][7]);
        }
        sPhiA[k][h] = P;
    } else if (t < (DEPTH - 1) * 16 + (DEPTH - 1) * 32) {  // PhiB: t bits 3..0 (x bit4)
        const int tt = t - (DEPTH - 1) * 16;
        const int k = tt >> 5, e4 = (tt >> 4) & 1, l = tt & 15;
        const int d = k + 1;
        const int mm = sM[d];
        const int gm = mm ^ (mm >> 1);
        float2 P = { 1.f, 0.f };
        #pragma unroll
        for (int i = 8; i <= 11; ++i)
            if ((l >> (11 - i)) & 1) P = cmul(P, sB1[d][i]);
        if (d >= 2) {
            if (((l >> 3) ^ e4       ^ (gm >> 3)) & 1) P = cmul(P, sG[d - 1][8]);
            if (((l >> 2) ^ (l >> 3) ^ (gm >> 2)) & 1) P = cmul(P, sG[d - 1][9]);
            if (((l >> 1) ^ (l >> 2) ^ (gm >> 1)) & 1) P = cmul(P, sG[d - 1][10]);
            if (((l >> 0) ^ (l >> 1) ^ (gm >> 0)) & 1) P = cmul(P, sG[d - 1][11]);
        }
        sPhiB[k][e4][l] = P;
    }
    if (t < (DEPTH - 1) * 32) {            // Thi: wires 0..3 (+ couplings 0..4)
        const int k = t / 32, e = (t >> 4) & 1, r = t & 15;
        const int d = k + 1;
        const int mm = sM[d];
        const int gm = mm ^ (mm >> 1);
        float2 T = { 1.f, 0.f };
        #pragma unroll
        for (int i = 0; i < 4; ++i)
            if ((r >> (3 - i)) & 1) T = cmul(T, sB1[d][i]);
        if (d >= 2) {
            int r0 = r & 1, r1 = (r >> 1) & 1, r2 = (r >> 2) & 1, r3 = (r >> 3) & 1;
            if ((r3      ^ (gm >> 11)) & 1) T = cmul(T, sG[d - 1][0]);
            if ((r2 ^ r3 ^ (gm >> 10)) & 1) T = cmul(T, sG[d - 1][1]);
            if ((r1 ^ r2 ^ (gm >>  9)) & 1) T = cmul(T, sG[d - 1][2]);
            if ((r0 ^ r1 ^ (gm >>  8)) & 1) T = cmul(T, sG[d - 1][3]);
            if ((e  ^ r0 ^ (gm >>  7)) & 1) T = cmul(T, sG[d - 1][4]);
        }
        sThiP[k][e][r] = T;
        sThiQ[k][e][r] = make_float2(-T.y, T.x);   // dual form
    }
    __syncthreads();

    // ================= Stage D: layer-1 fused table + per-thread phiF ======
    const int m1g = sM[1] ^ (sM[1] >> 1);
    if (t < 32) {
        const int e = t >> 4, r = t & 15;
        const int gr = (r ^ (r >> 1)) ^ ((m1g >> 8) & 15);
        float2 c01 = cmul(sU0[0][(gr & 8) ? 2 : 0], sU0[1][(gr & 4) ? 2 : 0]);
        float2 c23 = cmul(sU0[2][(gr & 2) ? 2 : 0], sU0[3][(gr & 1) ? 2 : 0]);
        float2 u4  = sU0[4][((e ^ r ^ (m1g >> 7)) & 1) ? 2 : 0];
        float2 W = cmul(cmul(c01, c23), cmul(u4, sThiP[0][0][r]));
        sW1P[e][r] = W;
        sW1Q[e][r] = make_float2(-W.y, W.x);       // dual form
    }
    const int gt = t ^ (t >> 1);
    float2 phiF;
    {
        float2 p = cmul(sPhiA[0][t >> 4], sPhiB[0][(t >> 4) & 1][t & 15]);
        const int gmix = gt ^ m1g;
        #pragma unroll
        for (int i = 5; i < NQ; ++i) {
            int bit = (gmix >> (11 - i)) & 1;
            p = cmul(p, sU0[i][bit ? 2 : 0]);
        }
        phiF = p;
    }
    __syncthreads();

    // ===== addressing bases (pad-17: phys = idx + (idx>>4)) ================
    const int swt_p   = t + (t >> 4);                              // C store: + 272r
    const int baseB_p = (((t >> 4) << 8) | (t & 15)) + ((t >> 4) << 4);  // B: + 17v
    const int baseA_p = 17 * t;                                    // A: + r

    u64 s[PT];                              // packed complex amplitudes

    // ================= Layer 1 (peeled): packed table multiply =============
    {
        const u64* w1P = reinterpret_cast<const u64*>(sW1P[t >> 7]);
        const u64* w1Q = reinterpret_cast<const u64*>(sW1Q[t >> 7]);
        const u64 pfx = pack2s(phiF.x), pfy = pack2s(phiF.y);
        #pragma unroll
        for (int r = 0; r < PT; ++r)
            s[r] = fma2(pfy, w1Q[r], mul2(pfx, w1P[r]));   // w1 * phiF, packed
        gate4p(s, sT[1][0], sT[1][1], sT[1][2], sT[1][3]);
        #pragma unroll
        for (int r = 0; r < PT; ++r)
            *reinterpret_cast<u64*>(&sS[swt_p + 272 * r]) = s[r];
        __syncthreads();

        #pragma unroll
        for (int r = 0; r < PT; ++r)
            s[r] = *reinterpret_cast<const u64*>(&sS[baseB_p + 17 * r]);
        gate4p(s, sT[1][4], sT[1][5], sT[1][6], sT[1][7]);
        #pragma unroll
        for (int r = 0; r < PT; ++r)
            *reinterpret_cast<u64*>(&sS[baseB_p + 17 * r]) = s[r];
        __syncwarp();

        #pragma unroll
        for (int r = 0; r < PT; ++r)
            s[r] = *reinterpret_cast<const u64*>(&sS[baseA_p + r]);
        gate4p(s, sT[1][8], sT[1][9], sT[1][10], sT[1][11]);
        #pragma unroll
        for (int r = 0; r < PT; ++r)
            *reinterpret_cast<u64*>(&sS[baseA_p + r]) = s[r];
        __syncthreads();
    }

    // ================= Layers 2..5 (fully unrolled) ========================
    #pragma unroll
    for (int d = 2; d < DEPTH; ++d) {
        const int k = d - 1;

        // ---- Round C: Gray gather + diagonal fused into load, wires 0..3 --
        {
            const int mm = sM[d];
            const int gIdx = gt ^ (mm ^ (mm >> 1));
            const float2 phi = cmul(sPhiA[k][t >> 4], sPhiB[k][(t >> 4) & 1][t & 15]);
            const u64 pxx = pack2s(phi.x), pyy = pack2s(phi.y);
            const u64* thiP = reinterpret_cast<const u64*>(sThiP[k][(t >> 7) & 1]);
            const u64* thiQ = reinterpret_cast<const u64*>(sThiQ[k][(t >> 7) & 1]);
            #pragma unroll
            for (int r = 0; r < PT; ++r) {
                const int gr = r ^ (r >> 1);
                const int cr = (gr << 8) ^ ((r & 1) << 7);   // logical src bits
                const int idxl = gIdx ^ cr;
                // w = phi * thi[r], packed (2 f32x2)
                float2 w = u2f(fma2(pyy, thiQ[r], mul2(pxx, thiP[r])));
                s[r] = f2u(cmul(sS[idxl + (idxl >> 4)], w));
            }
            __syncthreads();           // all reads of old state done
        }
        gate4p(s, sT[d][0], sT[d][1], sT[d][2], sT[d][3]);
        #pragma unroll
        for (int r = 0; r < PT; ++r)
            *reinterpret_cast<u64*>(&sS[swt_p + 272 * r]) = s[r];
        __syncthreads();

        // ---- Round B: wires 4..7 (per-thread disjoint addresses) ----
        #pragma unroll
        for (int r = 0; r < PT; ++r)
            s[r] = *reinterpret_cast<const u64*>(&sS[baseB_p + 17 * r]);
        gate4p(s, sT[d][4], sT[d][5], sT[d][6], sT[d][7]);
        #pragma unroll
        for (int r = 0; r < PT; ++r)
            *reinterpret_cast<u64*>(&sS[baseB_p + 17 * r]) = s[r];
        __syncwarp();                  // B->A exchange is within 16-thread groups

        // ---- Round A: wires 8..11 ----
        #pragma unroll
        for (int r = 0; r < PT; ++r)
            s[r] = *reinterpret_cast<const u64*>(&sS[baseA_p + r]);
        gate4p(s, sT[d][8], sT[d][9], sT[d][10], sT[d][11]);
        if (d < DEPTH - 1) {
            #pragma unroll
            for (int r = 0; r < PT; ++r)
                *reinterpret_cast<u64*>(&sS[baseA_p + r]) = s[r];
            __syncthreads();
        }
    }

    // ==== Final reduction directly from registers (idx = (t<<4)|r). ====
    float accLo[4] = { 0.f, 0.f, 0.f, 0.f };
    float sumAll = 0.f;
    #pragma unroll
    for (int r = 0; r < PT; ++r) {
        float2 a = u2f(s[r]);
        float pr = fmaf(a.x, a.x, a.y * a.y);
        sumAll += pr;
        const int r3 = (r >> 3) & 1, r2 = (r >> 2) & 1, r1 = (r >> 1) & 1, r0 = r & 1;
        const int p8 = r3, p9 = r3 ^ r2, p10 = p9 ^ r1, p11 = p10 ^ r0;
        accLo[0] += p8  ? -pr : pr;
        accLo[1] += p9  ? -pr : pr;
        accLo[2] += p10 ? -pr : pr;
        accLo[3] += p11 ? -pr : pr;
    }

    float acc[NQ];
    int pref = 0;
    #pragma unroll
    for (int q = 0; q < 8; ++q) {
        pref ^= (t >> (7 - q)) & 1;
        acc[q] = pref ? -sumAll : sumAll;
    }
    const int ptp = pref;
    #pragma unroll
    for (int q = 0; q < 4; ++q) acc[8 + q] = ptp ? -accLo[q] : accLo[q];

    #pragma unroll
    for (int q = 0; q < NQ; ++q) {
        #pragma unroll
        for (int off = 16; off; off >>= 1)
            acc[q] += __shfl_xor_sync(0xffffffffu, acc[q], off);
    }
    if ((t & 31) == 0) {
        #pragma unroll
        for (int q = 0; q < NQ; ++q) sRed[t >> 5][q] = acc[q];
    }
    __syncthreads();
    if (t < NQ) {
        float sres = 0.f;
        #pragma unroll
        for (int w = 0; w < NT / 32; ++w) sres += sRed[w][t];
        out[b * NQ + t] = sres;
    }
}

} // namespace

extern "C" void kernel_launch(void* const* d_in, const int* in_sizes, int n_in,
                              void* d_out, int out_size)
{
    (void)n_in; (void)out_size;
    const float* x;
    const float* params;
    if (in_sizes[0] == DEPTH * NQ * 3) {
        params = (const float*)d_in[0];
        x      = (const float*)d_in[1];
    } else {
        x      = (const float*)d_in[0];
        params = (const float*)d_in[1];
    }
    qsim_kernel<<<4096, NT>>>(x, params, (float*)d_out);
}